// round 15
// baseline (speedup 1.0000x reference)
#include <cuda_runtime.h>
#include <cuda_fp16.h>
#include <math.h>
#include <stdint.h>

#define D_DIM   128
#define NBINS   4096
#define SMIN    (-8.0f)
#define SRANGE  16.0f
#define WBIN    (SRANGE / (float)NBINS)
#define TARGETE 5.0f
#define EPSV    1e-7f

#define MAXN 65536
#define MAXB 4096

// fp16 operand scratch (no allocs allowed)
__device__ __align__(16) __half g_bank_h[(size_t)MAXN * D_DIM];
__device__ __align__(16) __half g_pts_h[(size_t)MAXB * D_DIM];

// ===========================================================================
// helpers
// ===========================================================================
__device__ __forceinline__ uint32_t smem_u32(const void* p) {
    uint32_t a;
    asm("{ .reg .u64 t; cvta.to.shared.u64 t, %1; cvt.u32.u64 %0, t; }"
        : "=r"(a) : "l"(p));
    return a;
}

__device__ __forceinline__ void ldsm4(uint32_t* r, uint32_t addr) {
    asm volatile("ldmatrix.sync.aligned.m8n8.x4.shared.b16 {%0,%1,%2,%3}, [%4];"
        : "=r"(r[0]), "=r"(r[1]), "=r"(r[2]), "=r"(r[3]) : "r"(addr));
}

__device__ __forceinline__ void mma_fp16(float* d, const uint32_t* a,
                                         uint32_t b0, uint32_t b1) {
    asm("mma.sync.aligned.m16n8k16.row.col.f32.f16.f16.f32 "
        "{%0,%1,%2,%3}, {%4,%5,%6,%7}, {%8,%9}, {%0,%1,%2,%3};"
        : "+f"(d[0]), "+f"(d[1]), "+f"(d[2]), "+f"(d[3])
        : "r"(a[0]), "r"(a[1]), "r"(a[2]), "r"(a[3]), "r"(b0), "r"(b1));
}

#define CP_ASYNC16(sa, ga) \
    asm volatile("cp.async.cg.shared.global [%0], [%1], 16;" \
                 :: "r"(sa), "l"(ga))
#define CP_COMMIT()  asm volatile("cp.async.commit_group;" ::: "memory")
#define CP_WAIT0()   asm volatile("cp.async.wait_group 0;" ::: "memory")

// ===========================================================================
// Kernel 1: normalize points -> fp16 (+ zero output scalars)
// ===========================================================================
__global__ void normalize_split_kernel(const float* __restrict__ pts,
                                       float* loss, float* cm, float* em)
{
    int b = blockIdx.x, k = threadIdx.x;
    if (b == 0 && k == 0 && loss != nullptr) {
        *loss = 0.0f; *cm = 0.0f; *em = 0.0f;
    }
    float v  = pts[(size_t)b * D_DIM + k];
    float ss = v * v;
    #pragma unroll
    for (int o = 16; o; o >>= 1) ss += __shfl_xor_sync(0xffffffffu, ss, o);
    __shared__ float ws[4];
    if ((k & 31) == 0) ws[k >> 5] = ss;
    __syncthreads();
    float nv = v / sqrtf(ws[0] + ws[1] + ws[2] + ws[3]);
    g_pts_h[(size_t)b * D_DIM + k] = __float2half_rn(nv);
}

// ===========================================================================
// Kernel 2: bank -> fp16
// ===========================================================================
__global__ void bank_split_kernel(const float* __restrict__ bank, int total4)
{
    int i = blockIdx.x * blockDim.x + threadIdx.x;
    if (i >= total4) return;
    float4 v = reinterpret_cast<const float4*>(bank)[i];
    __half2* ph = reinterpret_cast<__half2*>(g_bank_h);
    ph[2*i + 0] = __half2(__float2half_rn(v.x), __float2half_rn(v.y));
    ph[2*i + 1] = __half2(__float2half_rn(v.z), __float2half_rn(v.w));
}

// ===========================================================================
// Kernel 3: classic-HMMA fp16 single-product GEMM.
// C[B,N] = P_h[B,128] * bank_h[N,128]^T
// CTA: 128x128 N-tile, 8 warps (2m x 4n), warp tile 64x32.
// B fragments register-hoisted; A double-buffered via cp.async.
// ===========================================================================
#define ABUF(buf)   ((buf) * 32768)
#define SM_BHI      65536
#define GEMM_SMEM   98304

__device__ __forceinline__ void prefetch_tile(uint32_t sdst,
                                              const __half* __restrict__ g,
                                              int row0, int tid)
{
    #pragma unroll
    for (int it = 0; it < 8; it++) {
        int idx = tid + it * 256;
        int row = idx >> 4, c = idx & 15;
        uint32_t sa = sdst + (uint32_t)(row * 256 + ((c ^ (row & 7)) << 4));
        const void* ga = g + (size_t)(row0 + row) * D_DIM + c * 8;
        CP_ASYNC16(sa, ga);
    }
}

__global__ void __launch_bounds__(256, 1)
gemm_mma_kernel(float* __restrict__ C, int Nn, int Bb)
{
    extern __shared__ char sm[];
    const uint32_t sb = smem_u32(sm);
    const int tid  = threadIdx.x;
    const int lane = tid & 31, warp = tid >> 5;
    const int wm   = warp >> 2;
    const int wn   = warp & 3;
    const int bn   = blockIdx.x << 7;

    const int tiles_per = (Bb >> 7) / 2;
    const int mt0 = blockIdx.y * tiles_per;

    prefetch_tile(sb + SM_BHI,  g_bank_h, bn, tid);
    prefetch_tile(sb + ABUF(0), g_pts_h, mt0 << 7, tid);
    CP_COMMIT();
    CP_WAIT0();
    __syncthreads();

    const int xr  = lane & 7;
    const int aRow = (lane & 7) + ((lane >> 3) & 1) * 8;
    const int aC   = (lane >> 4) & 1;
    const int bRow = (lane & 7) + ((lane >> 4) & 1) * 8;
    const int bC   = (lane >> 3) & 1;

    uint32_t aBase[4];
    #pragma unroll
    for (int mf = 0; mf < 4; mf++)
        aBase[mf] = (uint32_t)((wm * 64 + mf * 16 + aRow) * 256);

    uint32_t bfr[8][2][4];
    #pragma unroll
    for (int s = 0; s < 8; s++) {
        const uint32_t cB = (uint32_t)(((2 * s + bC) ^ xr) << 4);
        #pragma unroll
        for (int p = 0; p < 2; p++) {
            uint32_t bb = (uint32_t)((wn * 32 + p * 16 + bRow) * 256);
            ldsm4(bfr[s][p], sb + SM_BHI + bb + cB);
        }
    }

    for (int i = 0; i < tiles_per; i++) {
        const int buf = i & 1;
        if (i + 1 < tiles_per) {
            prefetch_tile(sb + ABUF(buf ^ 1), g_pts_h, (mt0 + i + 1) << 7, tid);
            CP_COMMIT();
        }

        float acc[4][4][4];
        #pragma unroll
        for (int mf = 0; mf < 4; mf++)
            #pragma unroll
            for (int nf = 0; nf < 4; nf++)
                #pragma unroll
                for (int e = 0; e < 4; e++) acc[mf][nf][e] = 0.0f;

        const uint32_t aB = sb + ABUF(buf);
        #pragma unroll
        for (int s = 0; s < 8; s++) {
            const uint32_t cA = (uint32_t)(((2 * s + aC) ^ xr) << 4);
            uint32_t ah[4][4];
            #pragma unroll
            for (int mf = 0; mf < 4; mf++)
                ldsm4(ah[mf], aB + aBase[mf] + cA);
            #pragma unroll
            for (int mf = 0; mf < 4; mf++)
                #pragma unroll
                for (int p = 0; p < 2; p++) {
                    mma_fp16(acc[mf][2*p],   ah[mf], bfr[s][p][0], bfr[s][p][1]);
                    mma_fp16(acc[mf][2*p+1], ah[mf], bfr[s][p][2], bfr[s][p][3]);
                }
        }

        const int bm = (mt0 + i) << 7;
        #pragma unroll
        for (int mf = 0; mf < 4; mf++) {
            int m = bm + wm * 64 + mf * 16 + (lane >> 2);
            size_t base0 = (size_t)m * (size_t)Nn + bn + wn * 32 + (lane & 3) * 2;
            size_t base8 = base0 + (size_t)8 * (size_t)Nn;
            #pragma unroll
            for (int nf = 0; nf < 4; nf++) {
                C[base0 + nf * 8]     = acc[mf][nf][0];
                C[base0 + nf * 8 + 1] = acc[mf][nf][1];
                C[base8 + nf * 8]     = acc[mf][nf][2];
                C[base8 + nf * 8 + 1] = acc[mf][nf][3];
            }
        }

        CP_WAIT0();
        __syncthreads();
    }
}

// ===========================================================================
// Kernel 4: per-row histogram + 13-iter binary search + outputs
// MLP-8 load batching; u32 atomics; positive handled by post-subtraction.
// ===========================================================================
__device__ __forceinline__ float block_sum_bcast(float v, float* red,
                                                 volatile float* out, int tid)
{
    #pragma unroll
    for (int o = 16; o; o >>= 1) v += __shfl_xor_sync(0xffffffffu, v, o);
    if ((tid & 31) == 0) red[tid >> 5] = v;
    __syncthreads();
    if (tid < 32) {
        float x = (tid < 16) ? red[tid] : 0.0f;
        #pragma unroll
        for (int o = 8; o; o >>= 1) x += __shfl_xor_sync(0xffffffffu, x, o);
        if (tid == 0) *out = x;
    }
    __syncthreads();
    return *out;
}

__device__ __forceinline__ void hist4(uint32_t* cnt, float4 q,
                                      float bs, float boff)
{
    int b0 = min(max((int)fmaf(q.x, bs, boff), 0), NBINS - 1);
    int b1 = min(max((int)fmaf(q.y, bs, boff), 0), NBINS - 1);
    int b2 = min(max((int)fmaf(q.z, bs, boff), 0), NBINS - 1);
    int b3 = min(max((int)fmaf(q.w, bs, boff), 0), NBINS - 1);
    atomicAdd(&cnt[b0], 1u);
    atomicAdd(&cnt[b1], 1u);
    atomicAdd(&cnt[b2], 1u);
    atomicAdd(&cnt[b3], 1u);
}

__global__ void __launch_bounds__(512)
entropy_kernel(const float* __restrict__ sims, const int* __restrict__ pidx,
               int Nn, float invB,
               float* __restrict__ loss_acc, float* __restrict__ cent_acc,
               float* __restrict__ ent_acc)
{
    __shared__ uint32_t cnt[NBINS];
    __shared__ float red[16];
    __shared__ float sS, sQ, sPos;

    const int b   = blockIdx.x;
    const int tid = threadIdx.x;
    const float* row = sims + (size_t)b * (size_t)Nn;
    const int pos = pidx[b];

    for (int i = tid; i < NBINS; i += 512) cnt[i] = 0u;
    if (tid == 0) sPos = __ldg(row + pos);
    __syncthreads();

    const float bs   = (float)NBINS / SRANGE;   // 256
    const float boff = -SMIN * bs;              // 2048

    // alignment-aware (row base may be 4 mod 16)
    int lead = (int)(((16u - ((uint32_t)(uintptr_t)row & 15u)) & 15u) >> 2);
    if (lead > Nn) lead = Nn;
    if (tid < lead) {
        float s = row[tid];
        int bi = min(max((int)fmaf(s, bs, boff), 0), NBINS - 1);
        atomicAdd(&cnt[bi], 1u);
    }
    const int nvec = (Nn - lead) >> 2;
    const float4* rv = reinterpret_cast<const float4*>(row + lead);

    // main loop: 8 independent 16B loads in flight before any atomic
    int v = tid;
    for (; v + 3584 < nvec; v += 4096) {
        float4 q0 = __ldg(rv + v);
        float4 q1 = __ldg(rv + v + 512);
        float4 q2 = __ldg(rv + v + 1024);
        float4 q3 = __ldg(rv + v + 1536);
        float4 q4 = __ldg(rv + v + 2048);
        float4 q5 = __ldg(rv + v + 2560);
        float4 q6 = __ldg(rv + v + 3072);
        float4 q7 = __ldg(rv + v + 3584);
        hist4(cnt, q0, bs, boff);
        hist4(cnt, q1, bs, boff);
        hist4(cnt, q2, bs, boff);
        hist4(cnt, q3, bs, boff);
        hist4(cnt, q4, bs, boff);
        hist4(cnt, q5, bs, boff);
        hist4(cnt, q6, bs, boff);
        hist4(cnt, q7, bs, boff);
    }
    for (; v < nvec; v += 512) {
        float4 q = __ldg(rv + v);
        hist4(cnt, q, bs, boff);
    }
    for (int j = lead + nvec * 4 + tid; j < Nn; j += 512) {
        float s = row[j];
        int bi = min(max((int)fmaf(s, bs, boff), 0), NBINS - 1);
        atomicAdd(&cnt[bi], 1u);
    }
    __syncthreads();

    // remove the positive element's contribution
    if (tid == 0) {
        int bi = min(max((int)fmaf(sPos, bs, boff), 0), NBINS - 1);
        cnt[bi] -= 1u;
    }
    __syncthreads();

    // hoist this thread's 8 bins into registers
    float creg[8], mreg[8];
    #pragma unroll
    for (int r = 0; r < 8; r++) {
        int i = tid + r * 512;
        creg[r] = (float)cnt[i];
        mreg[r] = SMIN + ((float)i + 0.5f) * WBIN;
    }

    float center = 5.0f, scale = 2.5f;
    float ent = 0.0f, Sfin = 1.0f;

    for (int it = 0; it < 14; it++) {
        float invT = 1.0f / center;
        float Ereg[8];
        float Sloc = 0.0f;
        #pragma unroll
        for (int r = 0; r < 8; r++) {
            float E = 0.0f;
            if (creg[r] > 0.0f) {
                E = __expf(mreg[r] * invT);
                Sloc += creg[r] * E;
            }
            Ereg[r] = E;
        }
        float S  = block_sum_bcast(Sloc, red, &sS, tid);
        float eS = EPSV * S;
        float Qloc = 0.0f;
        #pragma unroll
        for (int r = 0; r < 8; r++)
            if (creg[r] > 0.0f)
                Qloc += creg[r] * Ereg[r] * __logf(Ereg[r] + eS);
        float Q = block_sum_bcast(Qloc, red, &sQ, tid);
        ent  = __logf(S) - Q / S;
        Sfin = S;
        if (it < 13) {
            center += (ent < TARGETE) ? scale : -scale;
            scale *= 0.5f;
        }
    }

    if (tid == 0) {
        float Fp = expf(sPos / center);
        float p  = Fp / (Sfin + Fp);
        atomicAdd(loss_acc, -logf(p + EPSV) * invB);
        atomicAdd(cent_acc, center * invB);
        atomicAdd(ent_acc,  ent * invB);
    }
}

// ===========================================================================
// launch
// ===========================================================================
extern "C" void kernel_launch(void* const* d_in, const int* in_sizes, int n_in,
                              void* d_out, int out_size)
{
    const float* points = (const float*)d_in[0];
    const float* bank   = (const float*)d_in[1];
    const int*   pidx   = (const int*)d_in[2];

    const int B = in_sizes[0] / D_DIM;   // 2048
    const int N = in_sizes[1] / D_DIM;   // 65536
    float* out = (float*)d_out;

    size_t BN = (size_t)B * (size_t)N;
    float* sims;
    float* loss_p = nullptr; float* cm_p = nullptr; float* em_p = nullptr;
    if ((size_t)out_size >= BN + 3) {
        loss_p = out;
        sims   = out + 1;
        cm_p   = out + 1 + BN;
        em_p   = out + 2 + BN;
    } else {
        sims = out;
    }

    static int attr_set = 0;
    if (!attr_set) {
        cudaFuncSetAttribute(gemm_mma_kernel,
                             cudaFuncAttributeMaxDynamicSharedMemorySize,
                             GEMM_SMEM);
        attr_set = 1;
    }

    normalize_split_kernel<<<B, 128>>>(points, loss_p, cm_p, em_p);

    int total4 = N * (D_DIM / 4);
    bank_split_kernel<<<(total4 + 255) / 256, 256>>>(bank, total4);

    dim3 gg(N / 128, 2);
    gemm_mma_kernel<<<gg, 256, GEMM_SMEM>>>(sims, N, B);

    if (loss_p) {
        entropy_kernel<<<B, 512>>>(sims, pidx, N, 1.0f / (float)B,
                                   loss_p, cm_p, em_p);
    }
}

// round 16
// speedup vs baseline: 1.0115x; 1.0115x over previous
#include <cuda_runtime.h>
#include <cuda_fp16.h>
#include <math.h>
#include <stdint.h>

#define D_DIM   128
#define NBINS   4096
#define SMIN    (-8.0f)
#define SRANGE  16.0f
#define WBIN    (SRANGE / (float)NBINS)
#define TARGETE 5.0f
#define EPSV    1e-7f

#define MAXN 65536
#define MAXB 4096

// fp16 operand scratch (no allocs allowed)
__device__ __align__(16) __half g_bank_h[(size_t)MAXN * D_DIM];
__device__ __align__(16) __half g_pts_h[(size_t)MAXB * D_DIM];

// ===========================================================================
// helpers
// ===========================================================================
__device__ __forceinline__ uint32_t smem_u32(const void* p) {
    uint32_t a;
    asm("{ .reg .u64 t; cvta.to.shared.u64 t, %1; cvt.u32.u64 %0, t; }"
        : "=r"(a) : "l"(p));
    return a;
}

__device__ __forceinline__ void ldsm4(uint32_t* r, uint32_t addr) {
    asm volatile("ldmatrix.sync.aligned.m8n8.x4.shared.b16 {%0,%1,%2,%3}, [%4];"
        : "=r"(r[0]), "=r"(r[1]), "=r"(r[2]), "=r"(r[3]) : "r"(addr));
}

__device__ __forceinline__ void mma_fp16(float* d, const uint32_t* a,
                                         uint32_t b0, uint32_t b1) {
    asm("mma.sync.aligned.m16n8k16.row.col.f32.f16.f16.f32 "
        "{%0,%1,%2,%3}, {%4,%5,%6,%7}, {%8,%9}, {%0,%1,%2,%3};"
        : "+f"(d[0]), "+f"(d[1]), "+f"(d[2]), "+f"(d[3])
        : "r"(a[0]), "r"(a[1]), "r"(a[2]), "r"(a[3]), "r"(b0), "r"(b1));
}

#define CP_ASYNC16(sa, ga) \
    asm volatile("cp.async.cg.shared.global [%0], [%1], 16;" \
                 :: "r"(sa), "l"(ga))
#define CP_COMMIT()  asm volatile("cp.async.commit_group;" ::: "memory")
#define CP_WAIT0()   asm volatile("cp.async.wait_group 0;" ::: "memory")

// ===========================================================================
// Kernel 1: normalize points -> fp16 (+ zero output scalars)
// ===========================================================================
__global__ void normalize_split_kernel(const float* __restrict__ pts,
                                       float* loss, float* cm, float* em)
{
    int b = blockIdx.x, k = threadIdx.x;
    if (b == 0 && k == 0 && loss != nullptr) {
        *loss = 0.0f; *cm = 0.0f; *em = 0.0f;
    }
    float v  = pts[(size_t)b * D_DIM + k];
    float ss = v * v;
    #pragma unroll
    for (int o = 16; o; o >>= 1) ss += __shfl_xor_sync(0xffffffffu, ss, o);
    __shared__ float ws[4];
    if ((k & 31) == 0) ws[k >> 5] = ss;
    __syncthreads();
    float nv = v / sqrtf(ws[0] + ws[1] + ws[2] + ws[3]);
    g_pts_h[(size_t)b * D_DIM + k] = __float2half_rn(nv);
}

// ===========================================================================
// Kernel 2: bank -> fp16
// ===========================================================================
__global__ void bank_split_kernel(const float* __restrict__ bank, int total4)
{
    int i = blockIdx.x * blockDim.x + threadIdx.x;
    if (i >= total4) return;
    float4 v = reinterpret_cast<const float4*>(bank)[i];
    __half2* ph = reinterpret_cast<__half2*>(g_bank_h);
    ph[2*i + 0] = __half2(__float2half_rn(v.x), __float2half_rn(v.y));
    ph[2*i + 1] = __half2(__float2half_rn(v.z), __float2half_rn(v.w));
}

// ===========================================================================
// Kernel 3: classic-HMMA fp16 single-product GEMM.
// C[B,N] = P_h[B,128] * bank_h[N,128]^T
// CTA: 128x128 N-tile, 8 warps (2m x 4n), warp tile 64x32.
// B fragments register-hoisted; A double-buffered via cp.async.
// ===========================================================================
#define ABUF(buf)   ((buf) * 32768)
#define SM_BHI      65536
#define GEMM_SMEM   98304

__device__ __forceinline__ void prefetch_tile(uint32_t sdst,
                                              const __half* __restrict__ g,
                                              int row0, int tid)
{
    #pragma unroll
    for (int it = 0; it < 8; it++) {
        int idx = tid + it * 256;
        int row = idx >> 4, c = idx & 15;
        uint32_t sa = sdst + (uint32_t)(row * 256 + ((c ^ (row & 7)) << 4));
        const void* ga = g + (size_t)(row0 + row) * D_DIM + c * 8;
        CP_ASYNC16(sa, ga);
    }
}

__global__ void __launch_bounds__(256, 1)
gemm_mma_kernel(float* __restrict__ C, int Nn, int Bb)
{
    extern __shared__ char sm[];
    const uint32_t sb = smem_u32(sm);
    const int tid  = threadIdx.x;
    const int lane = tid & 31, warp = tid >> 5;
    const int wm   = warp >> 2;
    const int wn   = warp & 3;
    const int bn   = blockIdx.x << 7;

    const int tiles_per = (Bb >> 7) / 2;
    const int mt0 = blockIdx.y * tiles_per;

    prefetch_tile(sb + SM_BHI,  g_bank_h, bn, tid);
    prefetch_tile(sb + ABUF(0), g_pts_h, mt0 << 7, tid);
    CP_COMMIT();
    CP_WAIT0();
    __syncthreads();

    const int xr  = lane & 7;
    const int aRow = (lane & 7) + ((lane >> 3) & 1) * 8;
    const int aC   = (lane >> 4) & 1;
    const int bRow = (lane & 7) + ((lane >> 4) & 1) * 8;
    const int bC   = (lane >> 3) & 1;

    uint32_t aBase[4];
    #pragma unroll
    for (int mf = 0; mf < 4; mf++)
        aBase[mf] = (uint32_t)((wm * 64 + mf * 16 + aRow) * 256);

    uint32_t bfr[8][2][4];
    #pragma unroll
    for (int s = 0; s < 8; s++) {
        const uint32_t cB = (uint32_t)(((2 * s + bC) ^ xr) << 4);
        #pragma unroll
        for (int p = 0; p < 2; p++) {
            uint32_t bb = (uint32_t)((wn * 32 + p * 16 + bRow) * 256);
            ldsm4(bfr[s][p], sb + SM_BHI + bb + cB);
        }
    }

    for (int i = 0; i < tiles_per; i++) {
        const int buf = i & 1;
        if (i + 1 < tiles_per) {
            prefetch_tile(sb + ABUF(buf ^ 1), g_pts_h, (mt0 + i + 1) << 7, tid);
            CP_COMMIT();
        }

        float acc[4][4][4];
        #pragma unroll
        for (int mf = 0; mf < 4; mf++)
            #pragma unroll
            for (int nf = 0; nf < 4; nf++)
                #pragma unroll
                for (int e = 0; e < 4; e++) acc[mf][nf][e] = 0.0f;

        const uint32_t aB = sb + ABUF(buf);
        #pragma unroll
        for (int s = 0; s < 8; s++) {
            const uint32_t cA = (uint32_t)(((2 * s + aC) ^ xr) << 4);
            uint32_t ah[4][4];
            #pragma unroll
            for (int mf = 0; mf < 4; mf++)
                ldsm4(ah[mf], aB + aBase[mf] + cA);
            #pragma unroll
            for (int mf = 0; mf < 4; mf++)
                #pragma unroll
                for (int p = 0; p < 2; p++) {
                    mma_fp16(acc[mf][2*p],   ah[mf], bfr[s][p][0], bfr[s][p][1]);
                    mma_fp16(acc[mf][2*p+1], ah[mf], bfr[s][p][2], bfr[s][p][3]);
                }
        }

        const int bm = (mt0 + i) << 7;
        #pragma unroll
        for (int mf = 0; mf < 4; mf++) {
            int m = bm + wm * 64 + mf * 16 + (lane >> 2);
            size_t base0 = (size_t)m * (size_t)Nn + bn + wn * 32 + (lane & 3) * 2;
            size_t base8 = base0 + (size_t)8 * (size_t)Nn;
            #pragma unroll
            for (int nf = 0; nf < 4; nf++) {
                C[base0 + nf * 8]     = acc[mf][nf][0];
                C[base0 + nf * 8 + 1] = acc[mf][nf][1];
                C[base8 + nf * 8]     = acc[mf][nf][2];
                C[base8 + nf * 8 + 1] = acc[mf][nf][3];
            }
        }

        CP_WAIT0();
        __syncthreads();
    }
}

// ===========================================================================
// Kernel 4: per-row histogram + 13-iter binary search + outputs
// MLP-8 load batching; u32 atomics; positive handled by post-subtraction.
// ===========================================================================
__device__ __forceinline__ float block_sum_bcast(float v, float* red,
                                                 volatile float* out, int tid)
{
    #pragma unroll
    for (int o = 16; o; o >>= 1) v += __shfl_xor_sync(0xffffffffu, v, o);
    if ((tid & 31) == 0) red[tid >> 5] = v;
    __syncthreads();
    if (tid < 32) {
        float x = (tid < 16) ? red[tid] : 0.0f;
        #pragma unroll
        for (int o = 8; o; o >>= 1) x += __shfl_xor_sync(0xffffffffu, x, o);
        if (tid == 0) *out = x;
    }
    __syncthreads();
    return *out;
}

__device__ __forceinline__ void hist4(uint32_t* cnt, float4 q,
                                      float bs, float boff)
{
    int b0 = min(max((int)fmaf(q.x, bs, boff), 0), NBINS - 1);
    int b1 = min(max((int)fmaf(q.y, bs, boff), 0), NBINS - 1);
    int b2 = min(max((int)fmaf(q.z, bs, boff), 0), NBINS - 1);
    int b3 = min(max((int)fmaf(q.w, bs, boff), 0), NBINS - 1);
    atomicAdd(&cnt[b0], 1u);
    atomicAdd(&cnt[b1], 1u);
    atomicAdd(&cnt[b2], 1u);
    atomicAdd(&cnt[b3], 1u);
}

__global__ void __launch_bounds__(512)
entropy_kernel(const float* __restrict__ sims, const int* __restrict__ pidx,
               int Nn, float invB,
               float* __restrict__ loss_acc, float* __restrict__ cent_acc,
               float* __restrict__ ent_acc)
{
    __shared__ uint32_t cnt[NBINS];
    __shared__ float red[16];
    __shared__ float sS, sQ, sPos;

    const int b   = blockIdx.x;
    const int tid = threadIdx.x;
    const float* row = sims + (size_t)b * (size_t)Nn;
    const int pos = pidx[b];

    for (int i = tid; i < NBINS; i += 512) cnt[i] = 0u;
    if (tid == 0) sPos = __ldg(row + pos);
    __syncthreads();

    const float bs   = (float)NBINS / SRANGE;   // 256
    const float boff = -SMIN * bs;              // 2048

    // alignment-aware (row base may be 4 mod 16)
    int lead = (int)(((16u - ((uint32_t)(uintptr_t)row & 15u)) & 15u) >> 2);
    if (lead > Nn) lead = Nn;
    if (tid < lead) {
        float s = row[tid];
        int bi = min(max((int)fmaf(s, bs, boff), 0), NBINS - 1);
        atomicAdd(&cnt[bi], 1u);
    }
    const int nvec = (Nn - lead) >> 2;
    const float4* rv = reinterpret_cast<const float4*>(row + lead);

    // main loop: 8 independent 16B loads in flight before any atomic
    int v = tid;
    for (; v + 3584 < nvec; v += 4096) {
        float4 q0 = __ldg(rv + v);
        float4 q1 = __ldg(rv + v + 512);
        float4 q2 = __ldg(rv + v + 1024);
        float4 q3 = __ldg(rv + v + 1536);
        float4 q4 = __ldg(rv + v + 2048);
        float4 q5 = __ldg(rv + v + 2560);
        float4 q6 = __ldg(rv + v + 3072);
        float4 q7 = __ldg(rv + v + 3584);
        hist4(cnt, q0, bs, boff);
        hist4(cnt, q1, bs, boff);
        hist4(cnt, q2, bs, boff);
        hist4(cnt, q3, bs, boff);
        hist4(cnt, q4, bs, boff);
        hist4(cnt, q5, bs, boff);
        hist4(cnt, q6, bs, boff);
        hist4(cnt, q7, bs, boff);
    }
    for (; v < nvec; v += 512) {
        float4 q = __ldg(rv + v);
        hist4(cnt, q, bs, boff);
    }
    for (int j = lead + nvec * 4 + tid; j < Nn; j += 512) {
        float s = row[j];
        int bi = min(max((int)fmaf(s, bs, boff), 0), NBINS - 1);
        atomicAdd(&cnt[bi], 1u);
    }
    __syncthreads();

    // remove the positive element's contribution
    if (tid == 0) {
        int bi = min(max((int)fmaf(sPos, bs, boff), 0), NBINS - 1);
        cnt[bi] -= 1u;
    }
    __syncthreads();

    // hoist this thread's 8 bins into registers
    float creg[8], mreg[8];
    #pragma unroll
    for (int r = 0; r < 8; r++) {
        int i = tid + r * 512;
        creg[r] = (float)cnt[i];
        mreg[r] = SMIN + ((float)i + 0.5f) * WBIN;
    }

    float center = 5.0f, scale = 2.5f;
    float ent = 0.0f, Sfin = 1.0f;

    for (int it = 0; it < 14; it++) {
        float invT = 1.0f / center;
        float Ereg[8];
        float Sloc = 0.0f;
        #pragma unroll
        for (int r = 0; r < 8; r++) {
            float E = 0.0f;
            if (creg[r] > 0.0f) {
                E = __expf(mreg[r] * invT);
                Sloc += creg[r] * E;
            }
            Ereg[r] = E;
        }
        float S  = block_sum_bcast(Sloc, red, &sS, tid);
        float eS = EPSV * S;
        float Qloc = 0.0f;
        #pragma unroll
        for (int r = 0; r < 8; r++)
            if (creg[r] > 0.0f)
                Qloc += creg[r] * Ereg[r] * __logf(Ereg[r] + eS);
        float Q = block_sum_bcast(Qloc, red, &sQ, tid);
        ent  = __logf(S) - Q / S;
        Sfin = S;
        if (it < 13) {
            center += (ent < TARGETE) ? scale : -scale;
            scale *= 0.5f;
        }
    }

    if (tid == 0) {
        float Fp = expf(sPos / center);
        float p  = Fp / (Sfin + Fp);
        atomicAdd(loss_acc, -logf(p + EPSV) * invB);
        atomicAdd(cent_acc, center * invB);
        atomicAdd(ent_acc,  ent * invB);
    }
}

// ===========================================================================
// launch
// ===========================================================================
extern "C" void kernel_launch(void* const* d_in, const int* in_sizes, int n_in,
                              void* d_out, int out_size)
{
    const float* points = (const float*)d_in[0];
    const float* bank   = (const float*)d_in[1];
    const int*   pidx   = (const int*)d_in[2];

    const int B = in_sizes[0] / D_DIM;   // 2048
    const int N = in_sizes[1] / D_DIM;   // 65536
    float* out = (float*)d_out;

    size_t BN = (size_t)B * (size_t)N;
    float* sims;
    float* loss_p = nullptr; float* cm_p = nullptr; float* em_p = nullptr;
    if ((size_t)out_size >= BN + 3) {
        loss_p = out;
        sims   = out + 1;
        cm_p   = out + 1 + BN;
        em_p   = out + 2 + BN;
    } else {
        sims = out;
    }

    static int attr_set = 0;
    if (!attr_set) {
        cudaFuncSetAttribute(gemm_mma_kernel,
                             cudaFuncAttributeMaxDynamicSharedMemorySize,
                             GEMM_SMEM);
        attr_set = 1;
    }

    normalize_split_kernel<<<B, 128>>>(points, loss_p, cm_p, em_p);

    int total4 = N * (D_DIM / 4);
    bank_split_kernel<<<(total4 + 255) / 256, 256>>>(bank, total4);

    dim3 gg(N / 128, 2);
    gemm_mma_kernel<<<gg, 256, GEMM_SMEM>>>(sims, N, B);

    if (loss_p) {
        entropy_kernel<<<B, 512>>>(sims, pidx, N, 1.0f / (float)B,
                                   loss_p, cm_p, em_p);
    }
}